// round 13
// baseline (speedup 1.0000x reference)
#include <cuda_runtime.h>
#include <stdint.h>

// ---------------------------------------------------------------------------
// TwoWL: 2-layer 2-WL coloring, N=256, M=65536. Output: 3 float32 histograms.
// 4 kernels; internal phases chained by producer->consumer L2 flags
// (producers at low block ids; flags self-cleaned by the last kernel).
// ---------------------------------------------------------------------------

#define NN 256
#define MM 65536
#define TAB 131072                 // rc*512 + cc*2 + A
#define ATAB 1024
#define ATABMASK (ATAB - 1)

#define F1 0
#define F2 1
#define F3 2
#define F4 3
#define F5 4

__device__ unsigned int       g_flag[8];   // 0 at every kernel entry (self-clean)
__device__ unsigned int       g_done[8];

__device__ unsigned int       g_Abits[MM / 32];
__device__ unsigned long long g_rowsig0[NN];
__device__ unsigned long long g_colsig0[NN];
__device__ unsigned long long g_rowsig1[NN];
__device__ unsigned long long g_colsig1[NN];
__device__ unsigned int       g_minposA[TAB];
__device__ int                g_countA[TAB];
__device__ unsigned int       g_minposB[TAB];
__device__ int                g_countB[TAB];
__device__ unsigned int       g_aminpos[ATAB];
__device__ int                g_acount[ATAB];
__device__ int4               g_mark4[MM / 4];
__device__ int4               g_rank4[MM / 4];
__device__ int                g_bsum[64];

#define g_mark ((int*)g_mark4)
#define g_rank ((int*)g_rank4)

// ---------------------------------------------------------------------------
__device__ __forceinline__ void sig_done(int f, unsigned int nprod) {
    __syncthreads();
    if (threadIdx.x == 0) {
        __threadfence();
        if (atomicAdd(&g_done[f], 1u) == nprod - 1u)
            atomicExch(&g_flag[f], 1u);
    }
}

__device__ __forceinline__ void wait_flag(int f) {
    if (threadIdx.x == 0) {
        while (*(volatile unsigned int*)&g_flag[f] == 0u) __nanosleep(32);
        __threadfence();
    }
    __syncthreads();
}

__device__ __forceinline__ unsigned long long sm64(unsigned long long z) {
    z += 0x9E3779B97F4A7C15ULL;
    z = (z ^ (z >> 30)) * 0xBF58476D1CE4E5B9ULL;
    z = (z ^ (z >> 27)) * 0x94D049BB133111EBULL;
    return z ^ (z >> 31);
}

__device__ __forceinline__ unsigned int abit(int idx) {
    return (g_Abits[idx >> 5] >> (idx & 31)) & 1u;
}

__device__ __forceinline__ unsigned int atomic_key(const int* __restrict__ x, int idx) {
    int i = idx >> 8;
    int j = idx & 255;
    unsigned int key = ((unsigned int)x[i] << 5) | ((unsigned int)x[j] << 1) | abit(idx);
    return key & ATABMASK;
}

// class(t) = min u with s[u]==s[t], via 512-slot shared hash (deterministic).
__device__ __forceinline__ int classify256(const unsigned long long* s, int t,
                                           unsigned long long* hk, int* hm) {
    hk[t] = 0ULL; hk[t + 256] = 0ULL;
    hm[t] = 256;  hm[t + 256] = 256;
    __syncthreads();
    unsigned long long v = s[t] | 0x8000000000000000ULL;
    unsigned int h0 = (unsigned int)((v * 0xFF51AFD7ED558CCDULL) >> 55) & 511u;
    unsigned int h = h0;
    for (;;) {
        unsigned long long old = atomicCAS(&hk[h], 0ULL, v);
        if (old == 0ULL || old == v) break;
        h = (h + 1) & 511u;
    }
    __syncthreads();
    h = h0;
    while (hk[h] != v) h = (h + 1) & 511u;
    atomicMin(&hm[h], t);
    __syncthreads();
    return hm[h];
}

// sig block: computes multiset hash of labels for row/col `task` from table.
__device__ __forceinline__ void sig_reduce_store(unsigned long long h, int t,
                                                 bool isRow, int rc,
                                                 unsigned long long* rowsig,
                                                 unsigned long long* colsig) {
    __shared__ unsigned long long ws[8];
    int lane = t & 31, w = t >> 5;
    #pragma unroll
    for (int off = 16; off > 0; off >>= 1)
        h += __shfl_down_sync(0xFFFFFFFFu, h, off);
    if (lane == 0) ws[w] = h;
    __syncthreads();
    if (t < 8) {
        unsigned long long hh = ws[t];
        #pragma unroll
        for (int off = 4; off > 0; off >>= 1)
            hh += __shfl_down_sync(0xFFu, hh, off);
        if (t == 0) {
            if (isRow) rowsig[rc] = hh;
            else       colsig[rc] = hh;
        }
    }
}

// scan one 1024-int chunk (int4 x 256 threads); clears marks.
__device__ __forceinline__ void scan_block(int chunk, int t) {
    __shared__ int warp_sums[8];
    __shared__ int warp_excl[8];
    int lane = t & 31, w = t >> 5;
    int4 v = g_mark4[chunk * 256 + t];
    g_mark4[chunk * 256 + t] = make_int4(0, 0, 0, 0);
    int s01 = v.x + v.y;
    int s012 = s01 + v.z;
    int tot = s012 + v.w;
    int inc = tot;
    #pragma unroll
    for (int off = 1; off < 32; off <<= 1) {
        int n = __shfl_up_sync(0xFFFFFFFFu, inc, off);
        if (lane >= off) inc += n;
    }
    if (lane == 31) warp_sums[w] = inc;
    __syncthreads();
    if (t < 8) {
        int ws = warp_sums[t];
        int inc2 = ws;
        #pragma unroll
        for (int off = 1; off < 8; off <<= 1) {
            int n = __shfl_up_sync(0xFFu, inc2, off);
            if (t >= off) inc2 += n;
        }
        warp_excl[t] = inc2 - ws;
    }
    __syncthreads();
    int base = warp_excl[w] + inc - tot;
    int4 e;
    e.x = base;
    e.y = base + v.x;
    e.z = base + s01;
    e.w = base + s012;
    g_rank4[chunk * 256 + t] = e;
    if (t == 255) g_bsum[chunk] = warp_excl[7] + inc;
}

__device__ __forceinline__ void finish_block(int sb, int t,
                                             const unsigned int* minpos,
                                             const int* count,
                                             float* dst, int avail) {
    __shared__ int sh_boff[64];
    if (t < 32) {
        int v0 = g_bsum[2 * t];
        int v1 = g_bsum[2 * t + 1];
        int p = v0 + v1;
        int inc3 = p;
        #pragma unroll
        for (int off = 1; off < 32; off <<= 1) {
            int n = __shfl_up_sync(0xFFFFFFFFu, inc3, off);
            if (t >= off) inc3 += n;
        }
        int excl = inc3 - p;
        sh_boff[2 * t] = excl;
        sh_boff[2 * t + 1] = excl + v0;
    }
    __syncthreads();
    int s = sb * 256 + t;
    int c = count[s];
    if (c > 0) {
        unsigned int p = minpos[s] & (MM - 1);
        int r = (g_rank[p] + sh_boff[p >> 10]) & (MM - 1);
        if (r < avail) dst[r] = (float)c;
    }
}

// ---------------------------------------------------------------------------
// K12: [0,256) init+edges ->F1-> [256,512) insA ->F2->
//      [512,1024) sig0, [1024,1088) rankA->hist0
// ---------------------------------------------------------------------------
__global__ void __launch_bounds__(256)
kA(const int* __restrict__ x, const int* __restrict__ ei, int E,
   float* __restrict__ out, int out_size, int a0) {
    int b = blockIdx.x, t = threadIdx.x;
    if (b < 256) {
        if (b == 0) {
            for (int i = t; i < MM / 32; i += 256) g_Abits[i] = 0u;
            __syncthreads();
            for (int e = t; e < E; e += 256) {
                unsigned int s = (unsigned int)ei[e] & 255u;
                unsigned int d = (unsigned int)ei[E + e] & 255u;
                unsigned int idx = s * NN + d;
                atomicOr(&g_Abits[idx >> 5], 1u << (idx & 31));
            }
        } else {
            int gid = (b - 1) * 256 + t;
            int stride = 255 * 256;
            for (int i = gid; i < out_size; i += stride) out[i] = 0.0f;
            for (int i = gid; i < TAB; i += stride) {
                g_minposA[i] = 0xFFFFFFFFu; g_countA[i] = 0;
                g_minposB[i] = 0xFFFFFFFFu; g_countB[i] = 0;
            }
            for (int i = gid; i < MM; i += stride) g_mark[i] = 0;
            if (gid < ATAB) { g_aminpos[gid] = 0xFFFFFFFFu; g_acount[gid] = 0; }
        }
        sig_done(F1, 256);
        return;
    }
    if (b < 512) {
        wait_flag(F1);
        int idx = (b - 256) * 256 + t;
        int i = idx >> 8;
        int j = idx & 255;
        unsigned int pos = (i == j) ? (unsigned int)(NN * (NN - 1) + i)
                                    : (unsigned int)(i * (NN - 1) + (j < i ? j : j - 1));
        unsigned int key = atomic_key(x, idx);
        atomicMin(&g_aminpos[key], pos);
        atomicAdd(&g_acount[key], 1);
        sig_done(F2, 256);
        return;
    }
    wait_flag(F2);
    if (b < 1024) {
        int task = b - 512;
        bool isRow = (task < NN);
        int rc = isRow ? task : task - NN;
        int idx = isRow ? ((rc << 8) + t) : ((t << 8) + rc);
        unsigned long long h =
            sm64((unsigned long long)g_aminpos[atomic_key(x, idx)]);
        sig_reduce_store(h, t, isRow, rc, g_rowsig0, g_colsig0);
        return;
    }
    // rankA -> hist0
    __shared__ unsigned int s[ATAB];
    #pragma unroll
    for (int u = 0; u < 4; u++) s[t + 256 * u] = g_aminpos[t + 256 * u];
    __syncthreads();
    int slot = (b - 1024) * 16 + (t >> 4);
    int lane16 = t & 15;
    unsigned int v = s[slot];
    int partial = 0;
    #pragma unroll 4
    for (int u = lane16; u < ATAB; u += 16) partial += (s[u] < v);
    #pragma unroll
    for (int off = 8; off > 0; off >>= 1)
        partial += __shfl_down_sync(0xFFFFFFFFu, partial, off, 16);
    if (lane16 == 0 && v != 0xFFFFFFFFu && partial < a0)
        out[partial] = (float)g_acount[slot];
}

// ---------------------------------------------------------------------------
// K3: [0,256) ins0 ->F3-> [256,768) sig1, [768,896) mark0 (grid-stride)
// ---------------------------------------------------------------------------
__global__ void __launch_bounds__(256)
kB() {
    int b = blockIdx.x, t = threadIdx.x;
    if (b < 256) {
        __shared__ unsigned long long srow[NN];
        __shared__ unsigned long long scol[NN];
        __shared__ unsigned long long hk[512];
        __shared__ int hm[512];
        __shared__ int rc_sh;
        srow[t] = g_rowsig0[t];
        scol[t] = g_colsig0[t];
        if (t == 0) rc_sh = 256;
        __syncthreads();
        if (srow[t] == srow[b]) atomicMin(&rc_sh, t);
        int cc = classify256(scol, t, hk, hm);
        __syncthreads();
        int idx = (b << 8) + t;
        unsigned int key = (unsigned int)rc_sh * 512u + (unsigned int)cc * 2u + abit(idx);
        atomicMin(&g_minposA[key], (unsigned int)idx);
        atomicAdd(&g_countA[key], 1);
        sig_done(F3, 256);
        return;
    }
    wait_flag(F3);
    if (b < 768) {
        __shared__ unsigned long long srow[NN];
        __shared__ unsigned long long scol[NN];
        __shared__ unsigned long long hk[512];
        __shared__ int hm[512];
        __shared__ int own_sh;
        int task = b - 256;
        srow[t] = g_rowsig0[t];
        scol[t] = g_colsig0[t];
        if (t == 0) own_sh = 256;
        __syncthreads();
        bool isRow = (task < NN);
        int rcix = isRow ? task : task - NN;
        unsigned int lab;
        if (isRow) {
            if (srow[t] == srow[rcix]) atomicMin(&own_sh, t);
            int cc = classify256(scol, t, hk, hm);
            __syncthreads();
            int idx = (rcix << 8) + t;
            unsigned int key = (unsigned int)own_sh * 512u
                             + (unsigned int)cc * 2u + abit(idx);
            lab = g_minposA[key];
        } else {
            if (scol[t] == scol[rcix]) atomicMin(&own_sh, t);
            int rc = classify256(srow, t, hk, hm);
            __syncthreads();
            int idx = (t << 8) + rcix;
            unsigned int key = (unsigned int)rc * 512u
                             + (unsigned int)own_sh * 2u + abit(idx);
            lab = g_minposA[key];
        }
        sig_reduce_store(sm64((unsigned long long)lab), t, isRow, rcix,
                         g_rowsig1, g_colsig1);
        return;
    }
    // mark0: 128 blocks grid-stride over TAB
    for (int s = (b - 768) * 256 + t; s < TAB; s += 128 * 256) {
        if (g_countA[s] > 0) g_mark[g_minposA[s] & (MM - 1)] = 1;
    }
}

// ---------------------------------------------------------------------------
// K4: [0,256) ins1 + [256,320) scan0 ->F4->
//     [320,448) mark1 (grid-stride), [448,960) finish0 -> hist1
// ---------------------------------------------------------------------------
__global__ void __launch_bounds__(256)
kC(float* __restrict__ out1, int a1) {
    int b = blockIdx.x, t = threadIdx.x;
    if (b < 256) {
        __shared__ unsigned long long srow[NN];
        __shared__ unsigned long long scol[NN];
        __shared__ unsigned long long hk[512];
        __shared__ int hm[512];
        __shared__ int rc_sh;
        srow[t] = g_rowsig1[t];
        scol[t] = g_colsig1[t];
        if (t == 0) rc_sh = 256;
        __syncthreads();
        if (srow[t] == srow[b]) atomicMin(&rc_sh, t);
        int cc = classify256(scol, t, hk, hm);
        __syncthreads();
        int idx = (b << 8) + t;
        unsigned int key = (unsigned int)rc_sh * 512u + (unsigned int)cc * 2u + abit(idx);
        atomicMin(&g_minposB[key], (unsigned int)idx);
        atomicAdd(&g_countB[key], 1);
        sig_done(F4, 320);
        return;
    }
    if (b < 320) {
        scan_block(b - 256, t);
        sig_done(F4, 320);
        return;
    }
    wait_flag(F4);
    if (b < 448) {
        for (int s = (b - 320) * 256 + t; s < TAB; s += 128 * 256) {
            if (g_countB[s] > 0) g_mark[g_minposB[s] & (MM - 1)] = 1;
        }
        return;
    }
    finish_block(b - 448, t, g_minposA, g_countA, out1, a1);
}

// ---------------------------------------------------------------------------
// K5: [0,64) scan1 ->F5-> [64,576) finish1 -> hist2; last block self-cleans
//     all flags/counters so the next launch starts clean.
// ---------------------------------------------------------------------------
__global__ void __launch_bounds__(256)
kD(float* __restrict__ out2, int a2) {
    int b = blockIdx.x, t = threadIdx.x;
    if (b < 64) {
        scan_block(b, t);
        sig_done(F5, 64);
        return;
    }
    wait_flag(F5);
    finish_block(b - 64, t, g_minposB, g_countB, out2, a2);
    __syncthreads();
    if (t == 0) {
        if (atomicAdd(&g_done[5], 1u) == 511u) {
            #pragma unroll
            for (int f = 0; f < 8; f++) { g_flag[f] = 0u; g_done[f] = 0u; }
            __threadfence();
        }
    }
}

// ---------------------------------------------------------------------------
extern "C" void kernel_launch(void* const* d_in, const int* in_sizes, int n_in,
                              void* d_out, int out_size) {
    int xi = 0, ei_i = 1;
    if (n_in >= 2 && in_sizes[0] > in_sizes[1]) { xi = 1; ei_i = 0; }
    const int* x  = (const int*)d_in[xi];
    const int* ei = (const int*)d_in[ei_i];
    int E = in_sizes[ei_i] / 2;
    if (E == 4 * 8192) E = 8192;
    float* out = (float*)d_out;

    int a0 = out_size < MM ? out_size : MM;
    int a1 = out_size - MM;     if (a1 > MM) a1 = MM; if (a1 < 0) a1 = 0;
    int a2 = out_size - 2 * MM; if (a2 > MM) a2 = MM; if (a2 < 0) a2 = 0;

    kA<<<1088, 256>>>(x, ei, E, out, out_size, a0);
    kB<<<896, 256>>>();
    kC<<<960, 256>>>(out + MM, a1);
    kD<<<576, 256>>>(out + 2 * MM, a2);
}

// round 15
// speedup vs baseline: 1.0556x; 1.0556x over previous
#include <cuda_runtime.h>
#include <stdint.h>

// ---------------------------------------------------------------------------
// TwoWL: 2-layer 2-WL coloring, N=256, M=65536. Output: 3 float32 histograms.
// 9-launch pipeline. Group key of (i,j) at layer l+1 =
// (rowclass_l(i), colclass_l(j), A) -> direct 131072-entry table.
// Classes via shared-hash classify, amortized 4 tasks per 1024-thread block.
// ---------------------------------------------------------------------------

#define NN 256
#define MM 65536
#define TAB 131072                 // rc*512 + cc*2 + A
#define ATAB 1024
#define ATABMASK (ATAB - 1)
#define MSB64 0x8000000000000000ULL

__device__ unsigned int       g_Abits[MM / 32];
__device__ unsigned long long g_rowsig0[NN];
__device__ unsigned long long g_colsig0[NN];
__device__ unsigned long long g_rowsig1[NN];
__device__ unsigned long long g_colsig1[NN];
__device__ unsigned int       g_minposA[TAB];
__device__ int                g_countA[TAB];
__device__ unsigned int       g_minposB[TAB];
__device__ int                g_countB[TAB];
__device__ unsigned int       g_aminpos[ATAB];
__device__ int                g_acount[ATAB];
__device__ int4               g_mark4[MM / 4];
__device__ int4               g_rank4[MM / 4];
__device__ int                g_bsum[16];

#define g_mark ((int*)g_mark4)
#define g_rank ((int*)g_rank4)

__device__ __forceinline__ unsigned long long sm64(unsigned long long z) {
    z += 0x9E3779B97F4A7C15ULL;
    z = (z ^ (z >> 30)) * 0xBF58476D1CE4E5B9ULL;
    z = (z ^ (z >> 27)) * 0x94D049BB133111EBULL;
    return z ^ (z >> 31);
}

__device__ __forceinline__ unsigned int abit(int idx) {
    return (g_Abits[idx >> 5] >> (idx & 31)) & 1u;
}

__device__ __forceinline__ unsigned int atomic_key(const int* __restrict__ x, int idx) {
    int i = idx >> 8;
    int j = idx & 255;
    unsigned int key = ((unsigned int)x[i] << 5) | ((unsigned int)x[j] << 1) | abit(idx);
    return key & ATABMASK;
}

// ---------------------------------------------------------------------------
// L1: block 0 builds adjacency bitset; blocks 1..255 clear everything else.
// ---------------------------------------------------------------------------
__global__ void __launch_bounds__(256)
k_init_edges(float* out, int out_size, const int* __restrict__ ei, int E) {
    int b = blockIdx.x, t = threadIdx.x;
    if (b == 0) {
        for (int i = t; i < MM / 32; i += 256) g_Abits[i] = 0u;
        __syncthreads();
        for (int e = t; e < E; e += 256) {
            unsigned int s = (unsigned int)ei[e] & 255u;
            unsigned int d = (unsigned int)ei[E + e] & 255u;
            unsigned int idx = s * NN + d;
            atomicOr(&g_Abits[idx >> 5], 1u << (idx & 31));
        }
    } else {
        int gid = (b - 1) * 256 + t;
        int stride = 255 * 256;
        for (int i = gid; i < out_size; i += stride) out[i] = 0.0f;
        for (int i = gid; i < TAB; i += stride) {
            g_minposA[i] = 0xFFFFFFFFu; g_countA[i] = 0;
            g_minposB[i] = 0xFFFFFFFFu; g_countB[i] = 0;
        }
        for (int i = gid; i < MM; i += stride) g_mark[i] = 0;
        if (gid < ATAB) { g_aminpos[gid] = 0xFFFFFFFFu; g_acount[gid] = 0; }
    }
}

// ---------------------------------------------------------------------------
// L2: atomic-layer insert (64 blocks x 1024)
// ---------------------------------------------------------------------------
__global__ void __launch_bounds__(1024)
k_insA(const int* __restrict__ x) {
    int idx = blockIdx.x * 1024 + threadIdx.x;
    int i = idx >> 8;
    int j = idx & 255;
    unsigned int pos = (i == j) ? (unsigned int)(NN * (NN - 1) + i)
                                : (unsigned int)(i * (NN - 1) + (j < i ? j : j - 1));
    unsigned int key = atomic_key(x, idx);
    atomicMin(&g_aminpos[key], pos);
    atomicAdd(&g_acount[key], 1);
}

// ---------------------------------------------------------------------------
// L3: blocks 0-511 sig0 (256 thr/task); blocks 512-575 rankA -> hist0
// ---------------------------------------------------------------------------
__global__ void __launch_bounds__(256)
k_sig0_rankA(const int* __restrict__ x, float* __restrict__ out0, int a0) {
    int b = blockIdx.x, t = threadIdx.x;
    if (b < 512) {
        __shared__ unsigned long long ws[8];
        int lane = t & 31, w = t >> 5;
        bool isRow = (b < NN);
        int rc = isRow ? b : b - NN;
        int idx = isRow ? ((rc << 8) + t) : ((t << 8) + rc);
        unsigned long long h =
            sm64((unsigned long long)g_aminpos[atomic_key(x, idx)]);
        #pragma unroll
        for (int off = 16; off > 0; off >>= 1)
            h += __shfl_down_sync(0xFFFFFFFFu, h, off);
        if (lane == 0) ws[w] = h;
        __syncthreads();
        if (t < 8) {
            unsigned long long hh = ws[t];
            #pragma unroll
            for (int off = 4; off > 0; off >>= 1)
                hh += __shfl_down_sync(0xFFu, hh, off);
            if (t == 0) {
                if (isRow) g_rowsig0[rc] = hh;
                else       g_colsig0[rc] = hh;
            }
        }
        return;
    }
    __shared__ unsigned int s[ATAB];
    #pragma unroll
    for (int u = 0; u < 4; u++) s[t + 256 * u] = g_aminpos[t + 256 * u];
    __syncthreads();
    int slot = (b - 512) * 16 + (t >> 4);
    int lane16 = t & 15;
    unsigned int v = s[slot];
    int partial = 0;
    #pragma unroll 4
    for (int u = lane16; u < ATAB; u += 16) partial += (s[u] < v);
    #pragma unroll
    for (int off = 8; off > 0; off >>= 1)
        partial += __shfl_down_sync(0xFFFFFFFFu, partial, off, 16);
    if (lane16 == 0 && v != 0xFFFFFFFFu && partial < a0)
        out0[partial] = (float)g_acount[slot];
}

// ---------------------------------------------------------------------------
// Batched insert: block handles 4 rows (base = 4*b); classify cols once.
// ---------------------------------------------------------------------------
__device__ __forceinline__ void ins_batch4(int b, int t,
                                           const unsigned long long* rowsig,
                                           const unsigned long long* colsig,
                                           unsigned int* minpos, int* count) {
    __shared__ unsigned long long srow[NN];
    __shared__ unsigned long long scol[NN];
    __shared__ unsigned long long hk[512];
    __shared__ int hm[512];
    __shared__ int rc_sh[4];
    int rowbase = b * 4;
    if (t < 512) { hk[t] = 0ULL; hm[t] = 256; }
    if (t < 256) { srow[t] = rowsig[t]; scol[t] = colsig[t]; }
    if (t < 4) rc_sh[t] = 256;
    __syncthreads();
    int c = t & 255;
    unsigned long long v = scol[c] | MSB64;
    unsigned int h0 = (unsigned int)((v * 0xFF51AFD7ED558CCDULL) >> 55) & 511u;
    if (t < 256) {
        unsigned int h = h0;
        for (;;) {
            unsigned long long old = atomicCAS(&hk[h], 0ULL, v);
            if (old == 0ULL || old == v) break;
            h = (h + 1) & 511u;
        }
        #pragma unroll
        for (int r = 0; r < 4; r++)
            if (srow[t] == srow[rowbase + r]) atomicMin(&rc_sh[r], t);
    }
    __syncthreads();
    unsigned int h = h0;
    while (hk[h] != v) h = (h + 1) & 511u;
    if (t < 256) atomicMin(&hm[h], c);
    __syncthreads();
    int cc = hm[h];
    int g = t >> 8;
    int idx = ((rowbase + g) << 8) + c;
    unsigned int key = (unsigned int)rc_sh[g] * 512u + (unsigned int)cc * 2u + abit(idx);
    atomicMin(&minpos[key], (unsigned int)idx);
    atomicAdd(&count[key], 1);
}

// L4: layer0 -> table A (64 blocks x 1024)
__global__ void __launch_bounds__(1024)
k_ins0() {
    ins_batch4(blockIdx.x, threadIdx.x, g_rowsig0, g_colsig0, g_minposA, g_countA);
}

// ---------------------------------------------------------------------------
// Batched sig: block handles 4 tasks of the same kind.
// b<64: row tasks 4b..4b+3; b in [64,128): col tasks.
// ---------------------------------------------------------------------------
__device__ __forceinline__ void sig_batch4(int b, int t,
                                           const unsigned long long* rowsig,
                                           const unsigned long long* colsig,
                                           const unsigned int* minpos,
                                           unsigned long long* rowsig_o,
                                           unsigned long long* colsig_o) {
    __shared__ unsigned long long srow[NN];
    __shared__ unsigned long long scol[NN];
    __shared__ unsigned long long hk[512];
    __shared__ int hm[512];
    __shared__ int own_sh[4];
    __shared__ unsigned long long ws[32];
    bool isRow = (b < 64);
    int base = (isRow ? b : b - 64) * 4;
    if (t < 512) { hk[t] = 0ULL; hm[t] = 256; }
    if (t < 256) { srow[t] = rowsig[t]; scol[t] = colsig[t]; }
    if (t < 4) own_sh[t] = 256;
    __syncthreads();
    int e = t & 255;
    unsigned long long v = (isRow ? scol[e] : srow[e]) | MSB64;
    unsigned int h0 = (unsigned int)((v * 0xFF51AFD7ED558CCDULL) >> 55) & 511u;
    if (t < 256) {
        unsigned int h = h0;
        for (;;) {
            unsigned long long old = atomicCAS(&hk[h], 0ULL, v);
            if (old == 0ULL || old == v) break;
            h = (h + 1) & 511u;
        }
        const unsigned long long* own = isRow ? srow : scol;
        #pragma unroll
        for (int r = 0; r < 4; r++)
            if (own[t] == own[base + r]) atomicMin(&own_sh[r], t);
    }
    __syncthreads();
    unsigned int h = h0;
    while (hk[h] != v) h = (h + 1) & 511u;
    if (t < 256) atomicMin(&hm[h], e);
    __syncthreads();
    int oc = hm[h];                       // class of opposite-axis element e
    int g = t >> 8;                       // task slot 0..3
    unsigned int lab;
    if (isRow) {
        int idx = ((base + g) << 8) + e;
        lab = minpos[(unsigned int)own_sh[g] * 512u + (unsigned int)oc * 2u + abit(idx)];
    } else {
        int idx = (e << 8) + (base + g);
        lab = minpos[(unsigned int)oc * 512u + (unsigned int)own_sh[g] * 2u + abit(idx)];
    }
    unsigned long long hh = sm64((unsigned long long)lab);
    int lane = t & 31, w = t >> 5;
    #pragma unroll
    for (int off = 16; off > 0; off >>= 1)
        hh += __shfl_down_sync(0xFFFFFFFFu, hh, off);
    if (lane == 0) ws[w] = hh;
    __syncthreads();
    if (t < 32) {
        unsigned long long xval = ws[t];
        #pragma unroll
        for (int off = 4; off > 0; off >>= 1)
            xval += __shfl_down_sync(0xFFFFFFFFu, xval, off, 8);
        if ((t & 7) == 0) {
            int task = base + (t >> 3);
            if (isRow) rowsig_o[task] = xval;
            else       colsig_o[task] = xval;
        }
    }
}

// L5: blocks 0-127 sig1; blocks 128-255 mark0 (table A)
__global__ void __launch_bounds__(1024)
k_sig1_mark0() {
    int b = blockIdx.x, t = threadIdx.x;
    if (b < 128) {
        sig_batch4(b, t, g_rowsig0, g_colsig0, g_minposA, g_rowsig1, g_colsig1);
        return;
    }
    int s = (b - 128) * 1024 + t;
    if (g_countA[s] > 0) g_mark[g_minposA[s] & (MM - 1)] = 1;
}

// ---------------------------------------------------------------------------
// Scan one 4096-int chunk (1024 threads, int4); clears marks. 16 chunks.
// ---------------------------------------------------------------------------
__device__ __forceinline__ void scan_block1024(int chunk, int t) {
    __shared__ int warp_sums[32];
    int lane = t & 31, w = t >> 5;
    int4 v = g_mark4[chunk * 1024 + t];
    g_mark4[chunk * 1024 + t] = make_int4(0, 0, 0, 0);
    int s01 = v.x + v.y;
    int s012 = s01 + v.z;
    int tot = s012 + v.w;
    int inc = tot;
    #pragma unroll
    for (int off = 1; off < 32; off <<= 1) {
        int n = __shfl_up_sync(0xFFFFFFFFu, inc, off);
        if (lane >= off) inc += n;
    }
    if (lane == 31) warp_sums[w] = inc;
    __syncthreads();
    if (t < 32) {
        int wsv = warp_sums[t];
        int inc2 = wsv;
        #pragma unroll
        for (int off = 1; off < 32; off <<= 1) {
            int n = __shfl_up_sync(0xFFFFFFFFu, inc2, off);
            if (t >= off) inc2 += n;
        }
        warp_sums[t] = inc2 - wsv;     // exclusive warp prefix
    }
    __syncthreads();
    int base = warp_sums[w] + inc - tot;
    int4 eo;
    eo.x = base;
    eo.y = base + v.x;
    eo.z = base + s01;
    eo.w = base + s012;
    g_rank4[chunk * 1024 + t] = eo;
    if (t == 1023) g_bsum[chunk] = warp_sums[31] + inc;
}

// L6: blocks 0-63 ins1 (sig1 -> table B); blocks 64-79 scan0
__global__ void __launch_bounds__(1024)
k_ins1_scan0() {
    int b = blockIdx.x, t = threadIdx.x;
    if (b < 64) {
        ins_batch4(b, t, g_rowsig1, g_colsig1, g_minposB, g_countB);
        return;
    }
    scan_block1024(b - 64, t);
}

// ---------------------------------------------------------------------------
// finish: 1024 threads per block, 128 blocks cover TAB.
// NOTE: 16-lane scan uses mask 0xFFFF (only lanes 0-15 execute it).
// ---------------------------------------------------------------------------
__device__ __forceinline__ void finish_block1024(int sb, int t,
                                                 const unsigned int* minpos,
                                                 const int* count,
                                                 float* dst, int avail) {
    __shared__ int sh_boff[16];
    if (t < 16) {
        int v = g_bsum[t];
        int inc = v;
        #pragma unroll
        for (int off = 1; off < 16; off <<= 1) {
            int n = __shfl_up_sync(0x0000FFFFu, inc, off, 16);
            if (t >= off) inc += n;
        }
        sh_boff[t] = inc - v;
    }
    __syncthreads();
    int s = sb * 1024 + t;
    int c = count[s];
    if (c > 0) {
        unsigned int p = minpos[s] & (MM - 1);
        int r = (g_rank[p] + sh_boff[p >> 12]) & (MM - 1);
        if (r < avail) dst[r] = (float)c;
    }
}

// L7: blocks 0-127 mark1 (table B); blocks 128-255 finish0 (A -> hist1)
__global__ void __launch_bounds__(1024)
k_mark1_finish0(float* __restrict__ out1, int a1) {
    int b = blockIdx.x, t = threadIdx.x;
    if (b < 128) {
        int s = b * 1024 + t;
        if (g_countB[s] > 0) g_mark[g_minposB[s] & (MM - 1)] = 1;
        return;
    }
    finish_block1024(b - 128, t, g_minposA, g_countA, out1, a1);
}

// L8: scan1 (16 blocks x 1024)
__global__ void __launch_bounds__(1024)
k_scan1() {
    scan_block1024(blockIdx.x, threadIdx.x);
}

// L9: finish1 (table B -> hist2)
__global__ void __launch_bounds__(1024)
k_finish1(float* __restrict__ out2, int a2) {
    finish_block1024(blockIdx.x, threadIdx.x, g_minposB, g_countB, out2, a2);
}

// ---------------------------------------------------------------------------
extern "C" void kernel_launch(void* const* d_in, const int* in_sizes, int n_in,
                              void* d_out, int out_size) {
    int xi = 0, ei_i = 1;
    if (n_in >= 2 && in_sizes[0] > in_sizes[1]) { xi = 1; ei_i = 0; }
    const int* x  = (const int*)d_in[xi];
    const int* ei = (const int*)d_in[ei_i];
    int E = in_sizes[ei_i] / 2;
    if (E == 4 * 8192) E = 8192;
    float* out = (float*)d_out;

    int a0 = out_size < MM ? out_size : MM;
    int a1 = out_size - MM;     if (a1 > MM) a1 = MM; if (a1 < 0) a1 = 0;
    int a2 = out_size - 2 * MM; if (a2 > MM) a2 = MM; if (a2 < 0) a2 = 0;

    k_init_edges<<<256, 256>>>(out, out_size, ei, E);   // L1
    k_insA<<<64, 1024>>>(x);                            // L2
    k_sig0_rankA<<<576, 256>>>(x, out, a0);             // L3
    k_ins0<<<64, 1024>>>();                             // L4
    k_sig1_mark0<<<256, 1024>>>();                      // L5
    k_ins1_scan0<<<80, 1024>>>();                       // L6
    k_mark1_finish0<<<256, 1024>>>(out + MM, a1);       // L7
    k_scan1<<<16, 1024>>>();                            // L8
    k_finish1<<<128, 1024>>>(out + 2 * MM, a2);         // L9
}

// round 16
// speedup vs baseline: 1.1634x; 1.1021x over previous
#include <cuda_runtime.h>
#include <stdint.h>

// ---------------------------------------------------------------------------
// TwoWL: 2-layer 2-WL coloring, N=256, M=65536. Output: 3 float32 histograms.
// 9-launch pipeline. Group key of (i,j) at layer l+1 =
// (rowclass_l(i), colclass_l(j), A) -> direct 131072-entry table.
// Inserts aggregate in shared memory first (global atomic traffic /64).
// ---------------------------------------------------------------------------

#define NN 256
#define MM 65536
#define TAB 131072                 // rc*512 + cc*2 + A
#define ATAB 1024
#define ATABMASK (ATAB - 1)
#define MSB64 0x8000000000000000ULL

__device__ unsigned int       g_Abits[MM / 32];
__device__ unsigned long long g_rowsig0[NN];
__device__ unsigned long long g_colsig0[NN];
__device__ unsigned long long g_rowsig1[NN];
__device__ unsigned long long g_colsig1[NN];
__device__ unsigned int       g_minposA[TAB];
__device__ int                g_countA[TAB];
__device__ unsigned int       g_minposB[TAB];
__device__ int                g_countB[TAB];
__device__ unsigned int       g_aminpos[ATAB];
__device__ int                g_acount[ATAB];
__device__ int4               g_mark4[MM / 4];
__device__ int4               g_rank4[MM / 4];
__device__ int                g_bsum[16];

#define g_mark ((int*)g_mark4)
#define g_rank ((int*)g_rank4)

__device__ __forceinline__ unsigned long long sm64(unsigned long long z) {
    z += 0x9E3779B97F4A7C15ULL;
    z = (z ^ (z >> 30)) * 0xBF58476D1CE4E5B9ULL;
    z = (z ^ (z >> 27)) * 0x94D049BB133111EBULL;
    return z ^ (z >> 31);
}

__device__ __forceinline__ unsigned int abit(int idx) {
    return (g_Abits[idx >> 5] >> (idx & 31)) & 1u;
}

__device__ __forceinline__ unsigned int atomic_key(const int* __restrict__ x, int idx) {
    int i = idx >> 8;
    int j = idx & 255;
    unsigned int key = ((unsigned int)x[i] << 5) | ((unsigned int)x[j] << 1) | abit(idx);
    return key & ATABMASK;
}

// ---------------------------------------------------------------------------
// L1: block 0 builds adjacency bitset; blocks 1..255 clear everything else.
// ---------------------------------------------------------------------------
__global__ void __launch_bounds__(256)
k_init_edges(float* out, int out_size, const int* __restrict__ ei, int E) {
    int b = blockIdx.x, t = threadIdx.x;
    if (b == 0) {
        for (int i = t; i < MM / 32; i += 256) g_Abits[i] = 0u;
        __syncthreads();
        for (int e = t; e < E; e += 256) {
            unsigned int s = (unsigned int)ei[e] & 255u;
            unsigned int d = (unsigned int)ei[E + e] & 255u;
            unsigned int idx = s * NN + d;
            atomicOr(&g_Abits[idx >> 5], 1u << (idx & 31));
        }
    } else {
        int gid = (b - 1) * 256 + t;
        int stride = 255 * 256;
        for (int i = gid; i < out_size; i += stride) out[i] = 0.0f;
        for (int i = gid; i < TAB; i += stride) {
            g_minposA[i] = 0xFFFFFFFFu; g_countA[i] = 0;
            g_minposB[i] = 0xFFFFFFFFu; g_countB[i] = 0;
        }
        for (int i = gid; i < MM; i += stride) g_mark[i] = 0;
        if (gid < ATAB) { g_aminpos[gid] = 0xFFFFFFFFu; g_acount[gid] = 0; }
    }
}

// ---------------------------------------------------------------------------
// L2: atomic-layer insert (64 blocks x 1024), shared-aggregated.
// ---------------------------------------------------------------------------
__global__ void __launch_bounds__(1024)
k_insA(const int* __restrict__ x) {
    __shared__ int          scnt[ATAB];
    __shared__ unsigned int sminp[ATAB];
    int t = threadIdx.x;
    scnt[t] = 0;
    sminp[t] = 0xFFFFFFFFu;
    __syncthreads();
    int idx = blockIdx.x * 1024 + t;
    int i = idx >> 8;
    int j = idx & 255;
    unsigned int pos = (i == j) ? (unsigned int)(NN * (NN - 1) + i)
                                : (unsigned int)(i * (NN - 1) + (j < i ? j : j - 1));
    unsigned int key = atomic_key(x, idx);
    atomicAdd(&scnt[key], 1);
    atomicMin(&sminp[key], pos);
    __syncthreads();
    int c = scnt[t];
    if (c > 0) {
        atomicMin(&g_aminpos[t], sminp[t]);
        atomicAdd(&g_acount[t], c);
    }
}

// ---------------------------------------------------------------------------
// L3: blocks 0-511 sig0 (256 thr/task); blocks 512-575 rankA -> hist0
// ---------------------------------------------------------------------------
__global__ void __launch_bounds__(256)
k_sig0_rankA(const int* __restrict__ x, float* __restrict__ out0, int a0) {
    int b = blockIdx.x, t = threadIdx.x;
    if (b < 512) {
        __shared__ unsigned long long ws[8];
        int lane = t & 31, w = t >> 5;
        bool isRow = (b < NN);
        int rc = isRow ? b : b - NN;
        int idx = isRow ? ((rc << 8) + t) : ((t << 8) + rc);
        unsigned long long h =
            sm64((unsigned long long)g_aminpos[atomic_key(x, idx)]);
        #pragma unroll
        for (int off = 16; off > 0; off >>= 1)
            h += __shfl_down_sync(0xFFFFFFFFu, h, off);
        if (lane == 0) ws[w] = h;
        __syncthreads();
        if (t < 8) {
            unsigned long long hh = ws[t];
            #pragma unroll
            for (int off = 4; off > 0; off >>= 1)
                hh += __shfl_down_sync(0xFFu, hh, off);
            if (t == 0) {
                if (isRow) g_rowsig0[rc] = hh;
                else       g_colsig0[rc] = hh;
            }
        }
        return;
    }
    __shared__ unsigned int s[ATAB];
    #pragma unroll
    for (int u = 0; u < 4; u++) s[t + 256 * u] = g_aminpos[t + 256 * u];
    __syncthreads();
    int slot = (b - 512) * 16 + (t >> 4);
    int lane16 = t & 15;
    unsigned int v = s[slot];
    int partial = 0;
    #pragma unroll 4
    for (int u = lane16; u < ATAB; u += 16) partial += (s[u] < v);
    #pragma unroll
    for (int off = 8; off > 0; off >>= 1)
        partial += __shfl_down_sync(0xFFFFFFFFu, partial, off, 16);
    if (lane16 == 0 && v != 0xFFFFFFFFu && partial < a0)
        out0[partial] = (float)g_acount[slot];
}

// ---------------------------------------------------------------------------
// Batched insert (4 rows per 1024-thread block) with shared aggregation.
// Local key = g*512 + cc*2 + A (2048 entries); flush to global per block.
// ---------------------------------------------------------------------------
__device__ __forceinline__ void ins_batch4(int b, int t,
                                           const unsigned long long* rowsig,
                                           const unsigned long long* colsig,
                                           unsigned int* minpos, int* count) {
    __shared__ unsigned long long srow[NN];
    __shared__ unsigned long long scol[NN];
    __shared__ unsigned long long hk[512];
    __shared__ int hm[512];
    __shared__ int rc_sh[4];
    __shared__ int scnt[2048];
    __shared__ int sminc[2048];
    int rowbase = b * 4;
    if (t < 512) { hk[t] = 0ULL; hm[t] = 256; }
    if (t < 256) { srow[t] = rowsig[t]; scol[t] = colsig[t]; }
    if (t < 4) rc_sh[t] = 256;
    #pragma unroll
    for (int u = 0; u < 2; u++) { scnt[t + 1024 * u] = 0; sminc[t + 1024 * u] = 256; }
    __syncthreads();
    int c = t & 255;
    unsigned long long v = scol[c] | MSB64;
    unsigned int h0 = (unsigned int)((v * 0xFF51AFD7ED558CCDULL) >> 55) & 511u;
    if (t < 256) {
        unsigned int h = h0;
        for (;;) {
            unsigned long long old = atomicCAS(&hk[h], 0ULL, v);
            if (old == 0ULL || old == v) break;
            h = (h + 1) & 511u;
        }
        #pragma unroll
        for (int r = 0; r < 4; r++)
            if (srow[t] == srow[rowbase + r]) atomicMin(&rc_sh[r], t);
    }
    __syncthreads();
    unsigned int h = h0;
    while (hk[h] != v) h = (h + 1) & 511u;
    if (t < 256) atomicMin(&hm[h], c);
    __syncthreads();
    int cc = hm[h];
    int g = t >> 8;
    int idx = ((rowbase + g) << 8) + c;
    int lk = (g << 9) + (cc << 1) + (int)abit(idx);
    atomicAdd(&scnt[lk], 1);
    atomicMin(&sminc[lk], c);
    __syncthreads();
    #pragma unroll
    for (int u = 0; u < 2; u++) {
        int lk2 = t + 1024 * u;
        int cnt = scnt[lk2];
        if (cnt > 0) {
            int g2 = lk2 >> 9;
            unsigned int key = (unsigned int)rc_sh[g2] * 512u + (unsigned int)(lk2 & 511);
            unsigned int gidx = ((unsigned int)(rowbase + g2) << 8) + (unsigned int)sminc[lk2];
            atomicMin(&minpos[key], gidx);
            atomicAdd(&count[key], cnt);
        }
    }
}

// L4: layer0 -> table A (64 blocks x 1024)
__global__ void __launch_bounds__(1024)
k_ins0() {
    ins_batch4(blockIdx.x, threadIdx.x, g_rowsig0, g_colsig0, g_minposA, g_countA);
}

// ---------------------------------------------------------------------------
// Batched sig: block handles 4 tasks of the same kind.
// b<64: row tasks 4b..4b+3; b in [64,128): col tasks.
// ---------------------------------------------------------------------------
__device__ __forceinline__ void sig_batch4(int b, int t,
                                           const unsigned long long* rowsig,
                                           const unsigned long long* colsig,
                                           const unsigned int* minpos,
                                           unsigned long long* rowsig_o,
                                           unsigned long long* colsig_o) {
    __shared__ unsigned long long srow[NN];
    __shared__ unsigned long long scol[NN];
    __shared__ unsigned long long hk[512];
    __shared__ int hm[512];
    __shared__ int own_sh[4];
    __shared__ unsigned long long ws[32];
    bool isRow = (b < 64);
    int base = (isRow ? b : b - 64) * 4;
    if (t < 512) { hk[t] = 0ULL; hm[t] = 256; }
    if (t < 256) { srow[t] = rowsig[t]; scol[t] = colsig[t]; }
    if (t < 4) own_sh[t] = 256;
    __syncthreads();
    int e = t & 255;
    unsigned long long v = (isRow ? scol[e] : srow[e]) | MSB64;
    unsigned int h0 = (unsigned int)((v * 0xFF51AFD7ED558CCDULL) >> 55) & 511u;
    if (t < 256) {
        unsigned int h = h0;
        for (;;) {
            unsigned long long old = atomicCAS(&hk[h], 0ULL, v);
            if (old == 0ULL || old == v) break;
            h = (h + 1) & 511u;
        }
        const unsigned long long* own = isRow ? srow : scol;
        #pragma unroll
        for (int r = 0; r < 4; r++)
            if (own[t] == own[base + r]) atomicMin(&own_sh[r], t);
    }
    __syncthreads();
    unsigned int h = h0;
    while (hk[h] != v) h = (h + 1) & 511u;
    if (t < 256) atomicMin(&hm[h], e);
    __syncthreads();
    int oc = hm[h];
    int g = t >> 8;
    unsigned int lab;
    if (isRow) {
        int idx = ((base + g) << 8) + e;
        lab = minpos[(unsigned int)own_sh[g] * 512u + (unsigned int)oc * 2u + abit(idx)];
    } else {
        int idx = (e << 8) + (base + g);
        lab = minpos[(unsigned int)oc * 512u + (unsigned int)own_sh[g] * 2u + abit(idx)];
    }
    unsigned long long hh = sm64((unsigned long long)lab);
    int lane = t & 31, w = t >> 5;
    #pragma unroll
    for (int off = 16; off > 0; off >>= 1)
        hh += __shfl_down_sync(0xFFFFFFFFu, hh, off);
    if (lane == 0) ws[w] = hh;
    __syncthreads();
    if (t < 32) {
        unsigned long long xval = ws[t];
        #pragma unroll
        for (int off = 4; off > 0; off >>= 1)
            xval += __shfl_down_sync(0xFFFFFFFFu, xval, off, 8);
        if ((t & 7) == 0) {
            int task = base + (t >> 3);
            if (isRow) rowsig_o[task] = xval;
            else       colsig_o[task] = xval;
        }
    }
}

// L5: blocks 0-127 sig1; blocks 128-255 mark0 (table A)
__global__ void __launch_bounds__(1024)
k_sig1_mark0() {
    int b = blockIdx.x, t = threadIdx.x;
    if (b < 128) {
        sig_batch4(b, t, g_rowsig0, g_colsig0, g_minposA, g_rowsig1, g_colsig1);
        return;
    }
    int s = (b - 128) * 1024 + t;
    if (g_countA[s] > 0) g_mark[g_minposA[s] & (MM - 1)] = 1;
}

// ---------------------------------------------------------------------------
// Scan one 4096-int chunk (1024 threads, int4); clears marks. 16 chunks.
// ---------------------------------------------------------------------------
__device__ __forceinline__ void scan_block1024(int chunk, int t) {
    __shared__ int warp_sums[32];
    int lane = t & 31, w = t >> 5;
    int4 v = g_mark4[chunk * 1024 + t];
    g_mark4[chunk * 1024 + t] = make_int4(0, 0, 0, 0);
    int s01 = v.x + v.y;
    int s012 = s01 + v.z;
    int tot = s012 + v.w;
    int inc = tot;
    #pragma unroll
    for (int off = 1; off < 32; off <<= 1) {
        int n = __shfl_up_sync(0xFFFFFFFFu, inc, off);
        if (lane >= off) inc += n;
    }
    if (lane == 31) warp_sums[w] = inc;
    __syncthreads();
    if (t < 32) {
        int wsv = warp_sums[t];
        int inc2 = wsv;
        #pragma unroll
        for (int off = 1; off < 32; off <<= 1) {
            int n = __shfl_up_sync(0xFFFFFFFFu, inc2, off);
            if (t >= off) inc2 += n;
        }
        warp_sums[t] = inc2 - wsv;
    }
    __syncthreads();
    int base = warp_sums[w] + inc - tot;
    int4 eo;
    eo.x = base;
    eo.y = base + v.x;
    eo.z = base + s01;
    eo.w = base + s012;
    g_rank4[chunk * 1024 + t] = eo;
    if (t == 1023) g_bsum[chunk] = warp_sums[31] + inc;
}

// L6: blocks 0-63 ins1 (sig1 -> table B); blocks 64-79 scan0
__global__ void __launch_bounds__(1024)
k_ins1_scan0() {
    int b = blockIdx.x, t = threadIdx.x;
    if (b < 64) {
        ins_batch4(b, t, g_rowsig1, g_colsig1, g_minposB, g_countB);
        return;
    }
    scan_block1024(b - 64, t);
}

// ---------------------------------------------------------------------------
// finish: 1024 threads per block, 128 blocks cover TAB.
// 16-lane scan uses mask 0xFFFF (only lanes 0-15 execute it).
// ---------------------------------------------------------------------------
__device__ __forceinline__ void finish_block1024(int sb, int t,
                                                 const unsigned int* minpos,
                                                 const int* count,
                                                 float* dst, int avail) {
    __shared__ int sh_boff[16];
    if (t < 16) {
        int v = g_bsum[t];
        int inc = v;
        #pragma unroll
        for (int off = 1; off < 16; off <<= 1) {
            int n = __shfl_up_sync(0x0000FFFFu, inc, off, 16);
            if (t >= off) inc += n;
        }
        sh_boff[t] = inc - v;
    }
    __syncthreads();
    int s = sb * 1024 + t;
    int c = count[s];
    if (c > 0) {
        unsigned int p = minpos[s] & (MM - 1);
        int r = (g_rank[p] + sh_boff[p >> 12]) & (MM - 1);
        if (r < avail) dst[r] = (float)c;
    }
}

// L7: blocks 0-127 mark1 (table B); blocks 128-255 finish0 (A -> hist1)
__global__ void __launch_bounds__(1024)
k_mark1_finish0(float* __restrict__ out1, int a1) {
    int b = blockIdx.x, t = threadIdx.x;
    if (b < 128) {
        int s = b * 1024 + t;
        if (g_countB[s] > 0) g_mark[g_minposB[s] & (MM - 1)] = 1;
        return;
    }
    finish_block1024(b - 128, t, g_minposA, g_countA, out1, a1);
}

// L8: scan1 (16 blocks x 1024)
__global__ void __launch_bounds__(1024)
k_scan1() {
    scan_block1024(blockIdx.x, threadIdx.x);
}

// L9: finish1 (table B -> hist2)
__global__ void __launch_bounds__(1024)
k_finish1(float* __restrict__ out2, int a2) {
    finish_block1024(blockIdx.x, threadIdx.x, g_minposB, g_countB, out2, a2);
}

// ---------------------------------------------------------------------------
extern "C" void kernel_launch(void* const* d_in, const int* in_sizes, int n_in,
                              void* d_out, int out_size) {
    int xi = 0, ei_i = 1;
    if (n_in >= 2 && in_sizes[0] > in_sizes[1]) { xi = 1; ei_i = 0; }
    const int* x  = (const int*)d_in[xi];
    const int* ei = (const int*)d_in[ei_i];
    int E = in_sizes[ei_i] / 2;
    if (E == 4 * 8192) E = 8192;
    float* out = (float*)d_out;

    int a0 = out_size < MM ? out_size : MM;
    int a1 = out_size - MM;     if (a1 > MM) a1 = MM; if (a1 < 0) a1 = 0;
    int a2 = out_size - 2 * MM; if (a2 > MM) a2 = MM; if (a2 < 0) a2 = 0;

    k_init_edges<<<256, 256>>>(out, out_size, ei, E);   // L1
    k_insA<<<64, 1024>>>(x);                            // L2
    k_sig0_rankA<<<576, 256>>>(x, out, a0);             // L3
    k_ins0<<<64, 1024>>>();                             // L4
    k_sig1_mark0<<<256, 1024>>>();                      // L5
    k_ins1_scan0<<<80, 1024>>>();                       // L6
    k_mark1_finish0<<<256, 1024>>>(out + MM, a1);       // L7
    k_scan1<<<16, 1024>>>();                            // L8
    k_finish1<<<128, 1024>>>(out + 2 * MM, a2);         // L9
}

// round 17
// speedup vs baseline: 1.3921x; 1.1965x over previous
#include <cuda_runtime.h>
#include <stdint.h>

// ---------------------------------------------------------------------------
// TwoWL: 2-layer 2-WL coloring, N=256, M=65536. Output: 3 float32 histograms.
// 7-launch pipeline. Key insight: group keys are injective labels, so
// signatures never wait on minpos tables; three histogram branches overlap.
//   key0 = (x_i<<5 | x_j<<1 | A)            -> layer-0 groups (direct 1024)
//   key1 = rc0*512 + cc0*2 + A              -> layer-1 groups (direct 131072)
//   key2 = rc1*512 + cc1*2 + A              -> layer-2 groups (direct 131072)
// ---------------------------------------------------------------------------

#define NN 256
#define MM 65536
#define TAB 131072
#define ATAB 1024
#define ATABMASK (ATAB - 1)
#define MSB64 0x8000000000000000ULL

__device__ unsigned int       g_Abits[MM / 32];
__device__ unsigned long long g_rowsig0[NN];
__device__ unsigned long long g_colsig0[NN];
__device__ unsigned long long g_rowsig1[NN];
__device__ unsigned long long g_colsig1[NN];
__device__ unsigned int       g_minposA[TAB];
__device__ int                g_countA[TAB];
__device__ unsigned int       g_minposB[TAB];
__device__ int                g_countB[TAB];
__device__ unsigned int       g_aminpos[ATAB];
__device__ int                g_acount[ATAB];
__device__ int4               g_markA4[MM / 4];
__device__ int4               g_markB4[MM / 4];
__device__ int4               g_scanA4[MM / 4];
__device__ int4               g_scanB4[MM / 4];
__device__ int                g_bsumA[16];
__device__ int                g_bsumB[16];

#define g_markA ((int*)g_markA4)
#define g_markB ((int*)g_markB4)
#define g_scanA ((int*)g_scanA4)
#define g_scanB ((int*)g_scanB4)

__device__ __forceinline__ unsigned long long sm64(unsigned long long z) {
    z += 0x9E3779B97F4A7C15ULL;
    z = (z ^ (z >> 30)) * 0xBF58476D1CE4E5B9ULL;
    z = (z ^ (z >> 27)) * 0x94D049BB133111EBULL;
    return z ^ (z >> 31);
}

__device__ __forceinline__ unsigned int abit(int idx) {
    return (g_Abits[idx >> 5] >> (idx & 31)) & 1u;
}

__device__ __forceinline__ unsigned int key0_of(const int* __restrict__ x, int idx) {
    int i = idx >> 8;
    int j = idx & 255;
    unsigned int key = ((unsigned int)x[i] << 5) | ((unsigned int)x[j] << 1) | abit(idx);
    return key & ATABMASK;
}

// ---------------------------------------------------------------------------
// K1: block 0 builds adjacency bitset; blocks 1..255 clear everything else.
// ---------------------------------------------------------------------------
__global__ void __launch_bounds__(256)
k1_init_edges(float* out, int out_size, const int* __restrict__ ei, int E) {
    int b = blockIdx.x, t = threadIdx.x;
    if (b == 0) {
        for (int i = t; i < MM / 32; i += 256) g_Abits[i] = 0u;
        __syncthreads();
        for (int e = t; e < E; e += 256) {
            unsigned int s = (unsigned int)ei[e] & 255u;
            unsigned int d = (unsigned int)ei[E + e] & 255u;
            unsigned int idx = s * NN + d;
            atomicOr(&g_Abits[idx >> 5], 1u << (idx & 31));
        }
    } else {
        int gid = (b - 1) * 256 + t;
        int stride = 255 * 256;
        for (int i = gid; i < out_size; i += stride) out[i] = 0.0f;
        for (int i = gid; i < TAB; i += stride) {
            g_minposA[i] = 0xFFFFFFFFu; g_countA[i] = 0;
            g_minposB[i] = 0xFFFFFFFFu; g_countB[i] = 0;
        }
        for (int i = gid; i < MM; i += stride) { g_markA[i] = 0; g_markB[i] = 0; }
        if (gid < ATAB) { g_aminpos[gid] = 0xFFFFFFFFu; g_acount[gid] = 0; }
    }
}

// ---------------------------------------------------------------------------
// K2: blocks 0-63 insA (shared-aggregated, 4 pairs/thread);
//     blocks 64-575 sig0 (label = key0, no table dependency).
// ---------------------------------------------------------------------------
__global__ void __launch_bounds__(256)
k2_insA_sig0(const int* __restrict__ x) {
    int b = blockIdx.x, t = threadIdx.x;
    if (b < 64) {
        __shared__ int          scnt[ATAB];
        __shared__ unsigned int sminp[ATAB];
        #pragma unroll
        for (int u = 0; u < 4; u++) { scnt[t + 256 * u] = 0; sminp[t + 256 * u] = 0xFFFFFFFFu; }
        __syncthreads();
        #pragma unroll
        for (int k = 0; k < 4; k++) {
            int idx = b * 1024 + k * 256 + t;
            int i = idx >> 8;
            int j = idx & 255;
            unsigned int pos = (i == j) ? (unsigned int)(NN * (NN - 1) + i)
                                        : (unsigned int)(i * (NN - 1) + (j < i ? j : j - 1));
            unsigned int key = key0_of(x, idx);
            atomicAdd(&scnt[key], 1);
            atomicMin(&sminp[key], pos);
        }
        __syncthreads();
        #pragma unroll
        for (int u = 0; u < 4; u++) {
            int s = t + 256 * u;
            int c = scnt[s];
            if (c > 0) {
                atomicMin(&g_aminpos[s], sminp[s]);
                atomicAdd(&g_acount[s], c);
            }
        }
        return;
    }
    // sig0: multiset hash of key0 over row/col
    __shared__ unsigned long long ws[8];
    int lane = t & 31, w = t >> 5;
    int task = b - 64;
    bool isRow = (task < NN);
    int rc = isRow ? task : task - NN;
    int idx = isRow ? ((rc << 8) + t) : ((t << 8) + rc);
    unsigned long long h = sm64((unsigned long long)key0_of(x, idx));
    #pragma unroll
    for (int off = 16; off > 0; off >>= 1)
        h += __shfl_down_sync(0xFFFFFFFFu, h, off);
    if (lane == 0) ws[w] = h;
    __syncthreads();
    if (t < 8) {
        unsigned long long hh = ws[t];
        #pragma unroll
        for (int off = 4; off > 0; off >>= 1)
            hh += __shfl_down_sync(0xFFu, hh, off);
        if (t == 0) {
            if (isRow) g_rowsig0[rc] = hh;
            else       g_colsig0[rc] = hh;
        }
    }
}

// ---------------------------------------------------------------------------
// Batched insert (4 rows per 1024-thread block) with shared aggregation.
// ---------------------------------------------------------------------------
__device__ __forceinline__ void ins_batch4(int b, int t,
                                           const unsigned long long* rowsig,
                                           const unsigned long long* colsig,
                                           unsigned int* minpos, int* count) {
    __shared__ unsigned long long srow[NN];
    __shared__ unsigned long long scol[NN];
    __shared__ unsigned long long hk[512];
    __shared__ int hm[512];
    __shared__ int rc_sh[4];
    __shared__ int scnt[2048];
    __shared__ int sminc[2048];
    int rowbase = b * 4;
    if (t < 512) { hk[t] = 0ULL; hm[t] = 256; }
    if (t < 256) { srow[t] = rowsig[t]; scol[t] = colsig[t]; }
    if (t < 4) rc_sh[t] = 256;
    #pragma unroll
    for (int u = 0; u < 2; u++) { scnt[t + 1024 * u] = 0; sminc[t + 1024 * u] = 256; }
    __syncthreads();
    int c = t & 255;
    unsigned long long v = scol[c] | MSB64;
    unsigned int h0 = (unsigned int)((v * 0xFF51AFD7ED558CCDULL) >> 55) & 511u;
    if (t < 256) {
        unsigned int h = h0;
        for (;;) {
            unsigned long long old = atomicCAS(&hk[h], 0ULL, v);
            if (old == 0ULL || old == v) break;
            h = (h + 1) & 511u;
        }
        #pragma unroll
        for (int r = 0; r < 4; r++)
            if (srow[t] == srow[rowbase + r]) atomicMin(&rc_sh[r], t);
    }
    __syncthreads();
    unsigned int h = h0;
    while (hk[h] != v) h = (h + 1) & 511u;
    if (t < 256) atomicMin(&hm[h], c);
    __syncthreads();
    int cc = hm[h];
    int g = t >> 8;
    int idx = ((rowbase + g) << 8) + c;
    int lk = (g << 9) + (cc << 1) + (int)abit(idx);
    atomicAdd(&scnt[lk], 1);
    atomicMin(&sminc[lk], c);
    __syncthreads();
    #pragma unroll
    for (int u = 0; u < 2; u++) {
        int lk2 = t + 1024 * u;
        int cnt = scnt[lk2];
        if (cnt > 0) {
            int g2 = lk2 >> 9;
            unsigned int key = (unsigned int)rc_sh[g2] * 512u + (unsigned int)(lk2 & 511);
            unsigned int gidx = ((unsigned int)(rowbase + g2) << 8) + (unsigned int)sminc[lk2];
            atomicMin(&minpos[key], gidx);
            atomicAdd(&count[key], cnt);
        }
    }
}

// ---------------------------------------------------------------------------
// Batched sig from classes (4 tasks/block, label = key1 inline, NO table load)
// b<64: row tasks; b in [64,128): col tasks.
// ---------------------------------------------------------------------------
__device__ __forceinline__ void sig_batch4(int b, int t,
                                           const unsigned long long* rowsig,
                                           const unsigned long long* colsig,
                                           unsigned long long* rowsig_o,
                                           unsigned long long* colsig_o) {
    __shared__ unsigned long long srow[NN];
    __shared__ unsigned long long scol[NN];
    __shared__ unsigned long long hk[512];
    __shared__ int hm[512];
    __shared__ int own_sh[4];
    __shared__ unsigned long long ws[32];
    bool isRow = (b < 64);
    int base = (isRow ? b : b - 64) * 4;
    if (t < 512) { hk[t] = 0ULL; hm[t] = 256; }
    if (t < 256) { srow[t] = rowsig[t]; scol[t] = colsig[t]; }
    if (t < 4) own_sh[t] = 256;
    __syncthreads();
    int e = t & 255;
    unsigned long long v = (isRow ? scol[e] : srow[e]) | MSB64;
    unsigned int h0 = (unsigned int)((v * 0xFF51AFD7ED558CCDULL) >> 55) & 511u;
    if (t < 256) {
        unsigned int h = h0;
        for (;;) {
            unsigned long long old = atomicCAS(&hk[h], 0ULL, v);
            if (old == 0ULL || old == v) break;
            h = (h + 1) & 511u;
        }
        const unsigned long long* own = isRow ? srow : scol;
        #pragma unroll
        for (int r = 0; r < 4; r++)
            if (own[t] == own[base + r]) atomicMin(&own_sh[r], t);
    }
    __syncthreads();
    unsigned int h = h0;
    while (hk[h] != v) h = (h + 1) & 511u;
    if (t < 256) atomicMin(&hm[h], e);
    __syncthreads();
    int oc = hm[h];
    int g = t >> 8;
    unsigned int lab;                       // label = key1 (injective per group)
    if (isRow) {
        int idx = ((base + g) << 8) + e;
        lab = (unsigned int)own_sh[g] * 512u + (unsigned int)oc * 2u + abit(idx);
    } else {
        int idx = (e << 8) + (base + g);
        lab = (unsigned int)oc * 512u + (unsigned int)own_sh[g] * 2u + abit(idx);
    }
    unsigned long long hh = sm64((unsigned long long)lab);
    int lane = t & 31, w = t >> 5;
    #pragma unroll
    for (int off = 16; off > 0; off >>= 1)
        hh += __shfl_down_sync(0xFFFFFFFFu, hh, off);
    if (lane == 0) ws[w] = hh;
    __syncthreads();
    if (t < 32) {
        unsigned long long xval = ws[t];
        #pragma unroll
        for (int off = 4; off > 0; off >>= 1)
            xval += __shfl_down_sync(0xFFFFFFFFu, xval, off, 8);
        if ((t & 7) == 0) {
            int task = base + (t >> 3);
            if (isRow) rowsig_o[task] = xval;
            else       colsig_o[task] = xval;
        }
    }
}

// ---------------------------------------------------------------------------
// K3: blocks 0-63 ins0 (key1 -> table A); blocks 64-191 sig1;
//     blocks 192-207 rankA -> hist0 (64 slots per block, 16 lanes each).
// ---------------------------------------------------------------------------
__global__ void __launch_bounds__(1024)
k3_ins0_sig1_rankA(float* __restrict__ out0, int a0) {
    int b = blockIdx.x, t = threadIdx.x;
    if (b < 64) {
        ins_batch4(b, t, g_rowsig0, g_colsig0, g_minposA, g_countA);
        return;
    }
    if (b < 192) {
        sig_batch4(b - 64, t, g_rowsig0, g_colsig0, g_rowsig1, g_colsig1);
        return;
    }
    __shared__ unsigned int s[ATAB];
    s[t] = g_aminpos[t];
    __syncthreads();
    int slot = (b - 192) * 64 + (t >> 4);
    int lane16 = t & 15;
    unsigned int v = s[slot];
    int partial = 0;
    #pragma unroll 4
    for (int u = lane16; u < ATAB; u += 16) partial += (s[u] < v);
    #pragma unroll
    for (int off = 8; off > 0; off >>= 1)
        partial += __shfl_down_sync(0xFFFFFFFFu, partial, off, 16);
    if (lane16 == 0 && v != 0xFFFFFFFFu && partial < a0)
        out0[partial] = (float)g_acount[slot];
}

// ---------------------------------------------------------------------------
// K4: blocks 0-63 ins1 (key2 -> table B); blocks 64-191 mark0 (A -> markA)
// ---------------------------------------------------------------------------
__global__ void __launch_bounds__(1024)
k4_ins1_mark0() {
    int b = blockIdx.x, t = threadIdx.x;
    if (b < 64) {
        ins_batch4(b, t, g_rowsig1, g_colsig1, g_minposB, g_countB);
        return;
    }
    int s = (b - 64) * 1024 + t;
    if (g_countA[s] > 0) g_markA[g_minposA[s] & (MM - 1)] = 1;
}

// ---------------------------------------------------------------------------
// Scan one 4096-int chunk of mark -> scan/bsum (no clearing; init does it).
// ---------------------------------------------------------------------------
__device__ __forceinline__ void scan_block1024(const int4* mark4, int4* scan4,
                                               int* bsum, int chunk, int t) {
    __shared__ int warp_sums[32];
    int lane = t & 31, w = t >> 5;
    int4 v = mark4[chunk * 1024 + t];
    int s01 = v.x + v.y;
    int s012 = s01 + v.z;
    int tot = s012 + v.w;
    int inc = tot;
    #pragma unroll
    for (int off = 1; off < 32; off <<= 1) {
        int n = __shfl_up_sync(0xFFFFFFFFu, inc, off);
        if (lane >= off) inc += n;
    }
    if (lane == 31) warp_sums[w] = inc;
    __syncthreads();
    if (t < 32) {
        int wsv = warp_sums[t];
        int inc2 = wsv;
        #pragma unroll
        for (int off = 1; off < 32; off <<= 1) {
            int n = __shfl_up_sync(0xFFFFFFFFu, inc2, off);
            if (t >= off) inc2 += n;
        }
        warp_sums[t] = inc2 - wsv;
    }
    __syncthreads();
    int base = warp_sums[w] + inc - tot;
    int4 eo;
    eo.x = base;
    eo.y = base + v.x;
    eo.z = base + s01;
    eo.w = base + s012;
    scan4[chunk * 1024 + t] = eo;
    if (t == 1023) bsum[chunk] = warp_sums[31] + inc;
}

// K5: blocks 0-15 scan0 (markA -> scanA); blocks 16-143 mark1 (B -> markB)
__global__ void __launch_bounds__(1024)
k5_scan0_mark1() {
    int b = blockIdx.x, t = threadIdx.x;
    if (b < 16) {
        scan_block1024(g_markA4, g_scanA4, g_bsumA, b, t);
        return;
    }
    int s = (b - 16) * 1024 + t;
    if (g_countB[s] > 0) g_markB[g_minposB[s] & (MM - 1)] = 1;
}

// ---------------------------------------------------------------------------
// finish: histogram for one table (16-lane masked scan of bsum).
// ---------------------------------------------------------------------------
__device__ __forceinline__ void finish_block1024(int sb, int t,
                                                 const unsigned int* minpos,
                                                 const int* count,
                                                 const int* scanv,
                                                 const int* bsum,
                                                 float* dst, int avail) {
    __shared__ int sh_boff[16];
    if (t < 16) {
        int v = bsum[t];
        int inc = v;
        #pragma unroll
        for (int off = 1; off < 16; off <<= 1) {
            int n = __shfl_up_sync(0x0000FFFFu, inc, off, 16);
            if (t >= off) inc += n;
        }
        sh_boff[t] = inc - v;
    }
    __syncthreads();
    int s = sb * 1024 + t;
    int c = count[s];
    if (c > 0) {
        unsigned int p = minpos[s] & (MM - 1);
        int r = (scanv[p] + sh_boff[p >> 12]) & (MM - 1);
        if (r < avail) dst[r] = (float)c;
    }
}

// K6: blocks 0-127 finish0 (A -> hist1); blocks 128-143 scan1 (markB -> scanB)
__global__ void __launch_bounds__(1024)
k6_finish0_scan1(float* __restrict__ out1, int a1) {
    int b = blockIdx.x, t = threadIdx.x;
    if (b < 128) {
        finish_block1024(b, t, g_minposA, g_countA, g_scanA, g_bsumA, out1, a1);
        return;
    }
    scan_block1024(g_markB4, g_scanB4, g_bsumB, b - 128, t);
}

// K7: finish1 (B -> hist2)
__global__ void __launch_bounds__(1024)
k7_finish1(float* __restrict__ out2, int a2) {
    finish_block1024(blockIdx.x, threadIdx.x, g_minposB, g_countB,
                     g_scanB, g_bsumB, out2, a2);
}

// ---------------------------------------------------------------------------
extern "C" void kernel_launch(void* const* d_in, const int* in_sizes, int n_in,
                              void* d_out, int out_size) {
    int xi = 0, ei_i = 1;
    if (n_in >= 2 && in_sizes[0] > in_sizes[1]) { xi = 1; ei_i = 0; }
    const int* x  = (const int*)d_in[xi];
    const int* ei = (const int*)d_in[ei_i];
    int E = in_sizes[ei_i] / 2;
    if (E == 4 * 8192) E = 8192;
    float* out = (float*)d_out;

    int a0 = out_size < MM ? out_size : MM;
    int a1 = out_size - MM;     if (a1 > MM) a1 = MM; if (a1 < 0) a1 = 0;
    int a2 = out_size - 2 * MM; if (a2 > MM) a2 = MM; if (a2 < 0) a2 = 0;

    k1_init_edges<<<256, 256>>>(out, out_size, ei, E);   // K1
    k2_insA_sig0<<<576, 256>>>(x);                       // K2
    k3_ins0_sig1_rankA<<<208, 1024>>>(out, a0);          // K3
    k4_ins1_mark0<<<192, 1024>>>();                      // K4
    k5_scan0_mark1<<<144, 1024>>>();                     // K5
    k6_finish0_scan1<<<144, 1024>>>(out + MM, a1);       // K6
    k7_finish1<<<128, 1024>>>(out + 2 * MM, a2);         // K7
}